// round 1
// baseline (speedup 1.0000x reference)
#include <cuda_runtime.h>

#define NB 32
#define NN 2000
#define NE 64000
#define ND 128
#define CHUNK 25

// ---------------- scratch (static device allocations; no cudaMalloc) ----------------
__device__ int   g_cnt[NN];        // in-degree counts (without self loop)
__device__ int   g_cursor[NN];     // CSR scatter cursors
__device__ float g_dinv[NN];       // rsqrt(deg+1)
__device__ float g_selfn[NN];      // dinv^2
__device__ float g_c[NN];          // pooling weight: selfn + sum of outgoing norm_e
__device__ int   g_rs[NN + 1];     // CSR row offsets (by dst)
__device__ int   g_csr_src[NE];
__device__ float g_csr_w[NE];
__device__ float g_v[NB * ND];     // weighted sum of relu'd layer-1 features
__device__ float g_h1[(size_t)NB * NN * ND];  // layer-1 linear output (32.8 MB)

// ---------------- small prep kernels ----------------
__global__ void k_init() {
    int i = blockIdx.x * blockDim.x + threadIdx.x;
    if (i < NN) { g_cnt[i] = 0; g_cursor[i] = 0; }
    if (i < NB * ND) g_v[i] = 0.f;
}

__global__ void k_count(const int* __restrict__ dst) {
    int e = blockIdx.x * blockDim.x + threadIdx.x;
    if (e < NE) atomicAdd(&g_cnt[dst[e]], 1);
}

__global__ void k_dinv() {
    int i = blockIdx.x * blockDim.x + threadIdx.x;
    if (i < NN) {
        float dg = (float)(g_cnt[i] + 1);
        float di = rsqrtf(dg);
        g_dinv[i]  = di;
        float sn   = di * di;
        g_selfn[i] = sn;
        g_c[i]     = sn;   // self-loop part of pooling weight
    }
}

__global__ void k_cout(const int* __restrict__ src, const int* __restrict__ dst) {
    int e = blockIdx.x * blockDim.x + threadIdx.x;
    if (e < NE) {
        float w = g_dinv[src[e]] * g_dinv[dst[e]];
        atomicAdd(&g_c[src[e]], w);
    }
}

// inclusive scan of g_cnt (N=2000 padded to 2048) -> row offsets
__global__ void k_scan() {
    __shared__ int s[2048];
    int t = threadIdx.x;  // 1024 threads
    s[t]        = (t < NN)        ? g_cnt[t]        : 0;
    s[t + 1024] = (t + 1024 < NN) ? g_cnt[t + 1024] : 0;
    __syncthreads();
    for (int off = 1; off < 2048; off <<= 1) {
        int v0 = (t >= off) ? s[t - off] : 0;
        int v1 = s[t + 1024 - off];   // t+1024 >= off always (off <= 1024)
        __syncthreads();
        s[t] += v0;
        s[t + 1024] += v1;
        __syncthreads();
    }
    if (t == 0) g_rs[0] = 0;
    if (t < NN) g_rs[t + 1] = s[t];
    if (t + 1024 < NN) g_rs[t + 1025] = s[t + 1024];
}

__global__ void k_scatter(const int* __restrict__ src, const int* __restrict__ dst) {
    int e = blockIdx.x * blockDim.x + threadIdx.x;
    if (e < NE) {
        int dd = dst[e], ss = src[e];
        int p = g_rs[dd] + atomicAdd(&g_cursor[dd], 1);
        g_csr_src[p] = ss;
        g_csr_w[p]   = g_dinv[ss] * g_dinv[dd];
    }
}

// ---------------- GEMM1: h1 = X(64000x128) @ W1(128x128), fp32 ----------------
// 64 rows per block, 256 threads, thread tile 8x4, k-tiled by 32 (24 KB static smem)
__global__ void k_gemm(const float* __restrict__ X, const float* __restrict__ W) {
    __shared__ float Ws[32 * 128];  // [kk][col]
    __shared__ float Xs[64 * 32];   // [row][kk]
    int tid = threadIdx.x;
    int tx = tid & 31;   // col group (4 cols each)
    int ty = tid >> 5;   // row group (8 rows each)
    size_t row0 = (size_t)blockIdx.x * 64;

    float acc[8][4];
#pragma unroll
    for (int i = 0; i < 8; i++)
#pragma unroll
        for (int j = 0; j < 4; j++) acc[i][j] = 0.f;

    for (int kt = 0; kt < 4; kt++) {
        const float4* Wg = (const float4*)(W + kt * 32 * 128);
        float4* Ws4 = (float4*)Ws;
#pragma unroll
        for (int i = 0; i < 4; i++) Ws4[tid + i * 256] = Wg[tid + i * 256];
#pragma unroll
        for (int i = 0; i < 8; i++) {
            int idx = tid + i * 256;          // 0..2047
            int r = idx >> 5, kk = idx & 31;  // warp covers one full 32-float row: coalesced
            Xs[idx] = X[(row0 + r) * 128 + kt * 32 + kk];
        }
        __syncthreads();
#pragma unroll
        for (int kk = 0; kk < 32; kk++) {
            float4 w4 = ((float4*)(Ws + kk * 128))[tx];
#pragma unroll
            for (int i = 0; i < 8; i++) {
                float xv = Xs[(ty * 8 + i) * 32 + kk];
                acc[i][0] = fmaf(xv, w4.x, acc[i][0]);
                acc[i][1] = fmaf(xv, w4.y, acc[i][1]);
                acc[i][2] = fmaf(xv, w4.z, acc[i][2]);
                acc[i][3] = fmaf(xv, w4.w, acc[i][3]);
            }
        }
        __syncthreads();
    }
#pragma unroll
    for (int i = 0; i < 8; i++) {
        size_t r = row0 + ty * 8 + i;
        float4 o = make_float4(acc[i][0], acc[i][1], acc[i][2], acc[i][3]);
        ((float4*)(g_h1 + r * 128))[tx] = o;
    }
}

// ---------------- fused layer-1 aggregation + bias + relu + weighted pool partial ----------------
// block = 128 threads (one per feature dim), handles one batch b and CHUNK dst nodes
__global__ void k_agg(const float* __restrict__ b1) {
    int b = blockIdx.y;
    int d = threadIdx.x;
    int dst0 = blockIdx.x * CHUNK;
    int dst1 = min(dst0 + CHUNK, NN);
    const float* __restrict__ hb = g_h1 + (size_t)b * NN * ND;
    float bias = b1[d];
    float vacc = 0.f;

    for (int dst = dst0; dst < dst1; ++dst) {
        float acc = fmaf(g_selfn[dst], hb[dst * ND + d], bias);
        int s = g_rs[dst], e = g_rs[dst + 1];
        int i = s;
        for (; i + 4 <= e; i += 4) {
            int s0 = g_csr_src[i], s1 = g_csr_src[i + 1];
            int s2 = g_csr_src[i + 2], s3 = g_csr_src[i + 3];
            float w0 = g_csr_w[i], w1 = g_csr_w[i + 1];
            float w2 = g_csr_w[i + 2], w3 = g_csr_w[i + 3];
            float h0 = hb[s0 * ND + d];
            float h1v = hb[s1 * ND + d];
            float h2v = hb[s2 * ND + d];
            float h3v = hb[s3 * ND + d];
            acc = fmaf(w0, h0, acc);
            acc = fmaf(w1, h1v, acc);
            acc = fmaf(w2, h2v, acc);
            acc = fmaf(w3, h3v, acc);
        }
        for (; i < e; ++i) acc = fmaf(g_csr_w[i], hb[g_csr_src[i] * ND + d], acc);
        acc = fmaxf(acc, 0.f);                 // relu
        vacc = fmaf(g_c[dst], acc, vacc);      // pooling weight
    }
    atomicAdd(&g_v[b * ND + d], vacc);
}

// ---------------- final: out[b,:] = (v[b,:]/N) @ W2 + b2 ----------------
__global__ void k_final(const float* __restrict__ W2, const float* __restrict__ b2,
                        float* __restrict__ out) {
    __shared__ float vs[ND];
    int b = blockIdx.x, d = threadIdx.x;
    vs[d] = g_v[b * ND + d] * (1.0f / NN);
    __syncthreads();
    float acc = b2[d];
#pragma unroll 8
    for (int k = 0; k < ND; k++) acc = fmaf(vs[k], W2[k * ND + d], acc);
    out[b * ND + d] = acc;
}

// ---------------- launch ----------------
extern "C" void kernel_launch(void* const* d_in, const int* in_sizes, int n_in,
                              void* d_out, int out_size) {
    const float* gene = (const float*)d_in[0];
    const int*   esrc = (const int*)d_in[1];
    const int*   edst = (const int*)d_in[2];
    const float* W1   = (const float*)d_in[3];
    const float* b1   = (const float*)d_in[4];
    const float* W2   = (const float*)d_in[5];
    const float* b2   = (const float*)d_in[6];
    float* out = (float*)d_out;

    k_init<<<(NB * ND + 255) / 256, 256>>>();
    k_count<<<(NE + 255) / 256, 256>>>(edst);
    k_dinv<<<(NN + 255) / 256, 256>>>();
    k_cout<<<(NE + 255) / 256, 256>>>(esrc, edst);
    k_scan<<<1, 1024>>>();
    k_scatter<<<(NE + 255) / 256, 256>>>(esrc, edst);
    k_gemm<<<(NB * NN) / 64, 256>>>(gene, W1);
    dim3 agrid((NN + CHUNK - 1) / CHUNK, NB);
    k_agg<<<agrid, ND>>>(b1);
    k_final<<<NB, ND>>>(W2, b2, out);
}

// round 3
// speedup vs baseline: 1.3941x; 1.3941x over previous
#include <cuda_runtime.h>
#include <cuda_fp16.h>

#define NB 32
#define NN 2000
#define NE 64000
#define ND 128
#define CHUNK 25

// ---------------- scratch ----------------
__device__ int    g_cnt[NN];
__device__ int    g_cursor[NN];
__device__ float  g_dinv[NN];
__device__ float  g_selfn[NN];
__device__ float  g_c[NN];
__device__ int    g_rs[NN + 1];
__device__ int2   g_csr[NE];            // (src, weight bits)
__device__ float  g_v[NB * ND];
__device__ __half g_h1[(size_t)NB * NN * ND];  // layer-1 output, fp16 (16.4 MB)

// ---------------- packed f32x2 helpers ----------------
__device__ __forceinline__ unsigned long long pk2(float lo, float hi) {
    unsigned long long r;
    asm("mov.b64 %0, {%1,%2};" : "=l"(r) : "f"(lo), "f"(hi));
    return r;
}
__device__ __forceinline__ void unpk2(unsigned long long v, float& lo, float& hi) {
    asm("mov.b64 {%0,%1}, %2;" : "=f"(lo), "=f"(hi) : "l"(v));
}
__device__ __forceinline__ void ffma2(unsigned long long& d,
                                      unsigned long long a, unsigned long long b) {
    asm("fma.rn.f32x2 %0, %1, %2, %0;" : "+l"(d) : "l"(a), "l"(b));
}
__device__ __forceinline__ unsigned int h2bits(__half2 h) {
    return *reinterpret_cast<unsigned int*>(&h);
}

// ---------------- prep kernels ----------------
__global__ void k_init() {
    int i = blockIdx.x * blockDim.x + threadIdx.x;
    if (i < NN) { g_cnt[i] = 0; g_cursor[i] = 0; }
    if (i < NB * ND) g_v[i] = 0.f;
}

__global__ void k_count(const int* __restrict__ dst) {
    int e = blockIdx.x * blockDim.x + threadIdx.x;
    if (e < NE) atomicAdd(&g_cnt[dst[e]], 1);
}

__global__ void k_dinv() {
    int i = blockIdx.x * blockDim.x + threadIdx.x;
    if (i < NN) {
        float di = rsqrtf((float)(g_cnt[i] + 1));
        g_dinv[i]  = di;
        float sn   = di * di;
        g_selfn[i] = sn;
        g_c[i]     = sn;   // self-loop part of pooling weight
    }
}

// inclusive scan of g_cnt (2000 padded to 2048) -> row offsets
__global__ void k_scan() {
    __shared__ int s[2048];
    int t = threadIdx.x;  // 1024 threads
    s[t]        = (t < NN)        ? g_cnt[t]        : 0;
    s[t + 1024] = (t + 1024 < NN) ? g_cnt[t + 1024] : 0;
    __syncthreads();
    for (int off = 1; off < 2048; off <<= 1) {
        int v0 = (t >= off) ? s[t - off] : 0;
        int v1 = s[t + 1024 - off];
        __syncthreads();
        s[t] += v0;
        s[t + 1024] += v1;
        __syncthreads();
    }
    if (t == 0) g_rs[0] = 0;
    if (t < NN) g_rs[t + 1] = s[t];
    if (t + 1024 < NN) g_rs[t + 1025] = s[t + 1024];
}

// scatter to CSR; also accumulate outgoing edge weight into pooling coeff g_c
__global__ void k_scatter(const int* __restrict__ src, const int* __restrict__ dst) {
    int e = blockIdx.x * blockDim.x + threadIdx.x;
    if (e < NE) {
        int dd = dst[e], ss = src[e];
        float w = g_dinv[ss] * g_dinv[dd];
        int p = g_rs[dd] + atomicAdd(&g_cursor[dd], 1);
        g_csr[p] = make_int2(ss, __float_as_int(w));
        atomicAdd(&g_c[ss], w);
    }
}

// ---------------- GEMM1: h1 = X(64000x128) @ W1(128x128), fp32 math, fp16 out ----------------
// 64 rows/block, 256 threads, thread tile = 4 row-pairs x 4 cols, packed f32x2 FMA
__global__ void k_gemm(const float* __restrict__ X, const float* __restrict__ W) {
    __shared__ float Ws[32 * 128];   // [kk][col]
    __shared__ float Xs[32 * 66];    // [kk][row], padded to 66 for LDS.64 alignment
    int tid = threadIdx.x;
    int tx = tid & 31;   // col group (4 cols)
    int ty = tid >> 5;   // row group (8 rows = 4 pairs)
    size_t row0 = (size_t)blockIdx.x * 64;

    unsigned long long acc[4][4];    // [row-pair][col], packed (r_lo, r_hi)
#pragma unroll
    for (int p = 0; p < 4; p++)
#pragma unroll
        for (int c = 0; c < 4; c++) acc[p][c] = 0ull;

    for (int kt = 0; kt < 4; kt++) {
        const float4* Wg = (const float4*)(W + kt * 32 * 128);
        float4* Ws4 = (float4*)Ws;
#pragma unroll
        for (int i = 0; i < 4; i++) Ws4[tid + i * 256] = Wg[tid + i * 256];
#pragma unroll
        for (int i = 0; i < 8; i++) {
            int idx = tid + i * 256;          // 0..2047
            int r = idx >> 5, kk = idx & 31;  // warp covers one row: coalesced gmem
            Xs[kk * 66 + r] = X[(row0 + r) * 128 + kt * 32 + kk];
        }
        __syncthreads();
#pragma unroll
        for (int kk = 0; kk < 32; kk++) {
            float4 w4 = *(const float4*)(Ws + kk * 128 + tx * 4);
            unsigned long long wd[4];
            wd[0] = pk2(w4.x, w4.x);
            wd[1] = pk2(w4.y, w4.y);
            wd[2] = pk2(w4.z, w4.z);
            wd[3] = pk2(w4.w, w4.w);
#pragma unroll
            for (int p = 0; p < 4; p++) {
                float2 xp = *(const float2*)(Xs + kk * 66 + ty * 8 + 2 * p);
                unsigned long long x2 = pk2(xp.x, xp.y);
                ffma2(acc[p][0], x2, wd[0]);
                ffma2(acc[p][1], x2, wd[1]);
                ffma2(acc[p][2], x2, wd[2]);
                ffma2(acc[p][3], x2, wd[3]);
            }
        }
        __syncthreads();
    }
    // store as fp16: rows (2p, 2p+1), cols 4*tx..4*tx+3
#pragma unroll
    for (int p = 0; p < 4; p++) {
        float lo0, hi0, lo1, hi1, lo2, hi2, lo3, hi3;
        unpk2(acc[p][0], lo0, hi0);
        unpk2(acc[p][1], lo1, hi1);
        unpk2(acc[p][2], lo2, hi2);
        unpk2(acc[p][3], lo3, hi3);
        size_t r0 = row0 + ty * 8 + 2 * p;
        __half2 a01 = __floats2half2_rn(lo0, lo1);
        __half2 a23 = __floats2half2_rn(lo2, lo3);
        __half2 b01 = __floats2half2_rn(hi0, hi1);
        __half2 b23 = __floats2half2_rn(hi2, hi3);
        uint2* out0 = (uint2*)(g_h1 + r0 * 128) + tx;
        uint2* out1 = (uint2*)(g_h1 + (r0 + 1) * 128) + tx;
        *out0 = make_uint2(h2bits(a01), h2bits(a23));
        *out1 = make_uint2(h2bits(b01), h2bits(b23));
    }
}

// ---------------- fused agg + bias + relu + weighted pool partial (fp16 gather) ----------------
// block = 64 threads (one half2 per thread = 128 dims), one batch x CHUNK dst nodes
__global__ void k_agg(const float* __restrict__ b1) {
    int b = blockIdx.y;
    int d2 = threadIdx.x;                   // 0..63
    int dst0 = blockIdx.x * CHUNK;
    int dst1 = min(dst0 + CHUNK, NN);
    const __half2* __restrict__ hb = (const __half2*)(g_h1 + (size_t)b * NN * ND);
    float bx = b1[2 * d2], by = b1[2 * d2 + 1];
    float vx = 0.f, vy = 0.f;

    for (int dst = dst0; dst < dst1; ++dst) {
        float sn = g_selfn[dst];
        float2 hs = __half22float2(hb[dst * 64 + d2]);
        float ax = fmaf(sn, hs.x, bx);
        float ay = fmaf(sn, hs.y, by);
        int s = g_rs[dst], e = g_rs[dst + 1];
        int i = s;
        for (; i + 4 <= e; i += 4) {
            int2 e0 = g_csr[i], e1 = g_csr[i + 1], e2 = g_csr[i + 2], e3 = g_csr[i + 3];
            float2 h0 = __half22float2(hb[e0.x * 64 + d2]);
            float2 h1v = __half22float2(hb[e1.x * 64 + d2]);
            float2 h2v = __half22float2(hb[e2.x * 64 + d2]);
            float2 h3v = __half22float2(hb[e3.x * 64 + d2]);
            float w0 = __int_as_float(e0.y), w1 = __int_as_float(e1.y);
            float w2 = __int_as_float(e2.y), w3 = __int_as_float(e3.y);
            ax = fmaf(w0, h0.x, ax);  ay = fmaf(w0, h0.y, ay);
            ax = fmaf(w1, h1v.x, ax); ay = fmaf(w1, h1v.y, ay);
            ax = fmaf(w2, h2v.x, ax); ay = fmaf(w2, h2v.y, ay);
            ax = fmaf(w3, h3v.x, ax); ay = fmaf(w3, h3v.y, ay);
        }
        for (; i < e; ++i) {
            int2 ee = g_csr[i];
            float2 h = __half22float2(hb[ee.x * 64 + d2]);
            float w = __int_as_float(ee.y);
            ax = fmaf(w, h.x, ax);
            ay = fmaf(w, h.y, ay);
        }
        ax = fmaxf(ax, 0.f);
        ay = fmaxf(ay, 0.f);
        float c = g_c[dst];
        vx = fmaf(c, ax, vx);
        vy = fmaf(c, ay, vy);
    }
    atomicAdd(&g_v[b * ND + 2 * d2],     vx);
    atomicAdd(&g_v[b * ND + 2 * d2 + 1], vy);
}

// ---------------- final: out[b,:] = (v[b,:]/N) @ W2 + b2 ----------------
__global__ void k_final(const float* __restrict__ W2, const float* __restrict__ b2,
                        float* __restrict__ out) {
    __shared__ float vs[ND];
    int b = blockIdx.x, d = threadIdx.x;
    vs[d] = g_v[b * ND + d] * (1.0f / NN);
    __syncthreads();
    float acc = b2[d];
#pragma unroll 8
    for (int k = 0; k < ND; k++) acc = fmaf(vs[k], W2[k * ND + d], acc);
    out[b * ND + d] = acc;
}

// ---------------- launch ----------------
extern "C" void kernel_launch(void* const* d_in, const int* in_sizes, int n_in,
                              void* d_out, int out_size) {
    const float* gene = (const float*)d_in[0];
    const int*   esrc = (const int*)d_in[1];
    const int*   edst = (const int*)d_in[2];
    const float* W1   = (const float*)d_in[3];
    const float* b1   = (const float*)d_in[4];
    const float* W2   = (const float*)d_in[5];
    const float* b2   = (const float*)d_in[6];
    float* out = (float*)d_out;

    k_init<<<(NB * ND + 255) / 256, 256>>>();
    k_count<<<(NE + 255) / 256, 256>>>(edst);
    k_dinv<<<(NN + 255) / 256, 256>>>();
    k_scan<<<1, 1024>>>();
    k_scatter<<<(NE + 255) / 256, 256>>>(esrc, edst);
    k_gemm<<<(NB * NN) / 64, 256>>>(gene, W1);
    dim3 agrid((NN + CHUNK - 1) / CHUNK, NB);
    k_agg<<<agrid, 64>>>(b1);
    k_final<<<NB, ND>>>(W2, b2, out);
}

// round 5
// speedup vs baseline: 1.5325x; 1.0993x over previous
#include <cuda_runtime.h>
#include <cuda_fp16.h>
#include <cstdint>

#define NB 32
#define NN 2000
#define NE 64000
#define ND 128
#define CHUNK 25

// ---------------- scratch ----------------
__device__ int    g_cnt[NN];
__device__ int    g_cursor[NN];
__device__ float  g_dinv[NN];
__device__ float  g_selfn[NN];
__device__ float  g_c[NN];
__device__ int    g_rs[NN + 1];
__device__ int2   g_csr[NE];            // (src*64, weight bits)
__device__ float  g_v[NB * ND];
__device__ __half g_w1h[ND * ND];       // W1 transposed, fp16: g_w1h[n*128+k] = W1[k,n]
__device__ __half g_h1[(size_t)NB * NN * ND];  // layer-1 output, fp16 (16.4 MB)

// ---------------- prep kernels ----------------
// zero g_cnt + build W1^T in fp16
__global__ void k_prep0(const float* __restrict__ W1) {
    int idx = blockIdx.x * blockDim.x + threadIdx.x;   // 64 blocks x 256
    if (idx < NN) g_cnt[idx] = 0;
    if (idx < ND * ND) {
        int n = idx >> 7, k = idx & 127;
        g_w1h[idx] = __float2half(W1[k * ND + n]);
    }
}

__global__ void k_count(const int* __restrict__ dst) {
    int e = blockIdx.x * blockDim.x + threadIdx.x;
    if (e < NE) atomicAdd(&g_cnt[dst[e]], 1);
}

// scan + dinv/selfn/c + zero cursor/v, single block 1024 threads
__global__ void k_scandinv() {
    __shared__ int s[2048];
    int t = threadIdx.x;
    s[t]        = (t < NN)        ? g_cnt[t]        : 0;
    s[t + 1024] = (t + 1024 < NN) ? g_cnt[t + 1024] : 0;
    __syncthreads();
    for (int off = 1; off < 2048; off <<= 1) {
        int v0 = (t >= off) ? s[t - off] : 0;
        int v1 = s[t + 1024 - off];
        __syncthreads();
        s[t] += v0;
        s[t + 1024] += v1;
        __syncthreads();
    }
    if (t == 0) g_rs[0] = 0;
    if (t < NN) g_rs[t + 1] = s[t];
    if (t + 1024 < NN) g_rs[t + 1025] = s[t + 1024];
    for (int i = t; i < NN; i += 1024) {
        float di = rsqrtf((float)(g_cnt[i] + 1));
        g_dinv[i]  = di;
        float sn   = di * di;
        g_selfn[i] = sn;
        g_c[i]     = sn;
        g_cursor[i] = 0;
    }
    for (int i = t; i < NB * ND; i += 1024) g_v[i] = 0.f;
}

__global__ void k_scatter(const int* __restrict__ src, const int* __restrict__ dst) {
    int e = blockIdx.x * blockDim.x + threadIdx.x;
    if (e < NE) {
        int dd = dst[e], ss = src[e];
        float w = g_dinv[ss] * g_dinv[dd];
        int p = g_rs[dd] + atomicAdd(&g_cursor[dd], 1);
        g_csr[p] = make_int2(ss * 64, __float_as_int(w));
        atomicAdd(&g_c[ss], w);
    }
}

// ---------------- GEMM1 via mma.sync (HMMA): h1 = X @ W1, fp16 in, fp32 acc ----------------
// CTA = 128x128, 8 warps; warp tile 32x64 (2 x 8 m16n8k16 fragments), K=128 in 8 chunks
#define AS_STRIDE 132   // halves per row (padded)

__device__ __forceinline__ void mma16816(float* c, const uint32_t* a, const uint32_t* b) {
    asm volatile(
        "mma.sync.aligned.m16n8k16.row.col.f32.f16.f16.f32 "
        "{%0,%1,%2,%3}, {%4,%5,%6,%7}, {%8,%9}, {%0,%1,%2,%3};"
        : "+f"(c[0]), "+f"(c[1]), "+f"(c[2]), "+f"(c[3])
        : "r"(a[0]), "r"(a[1]), "r"(a[2]), "r"(a[3]), "r"(b[0]), "r"(b[1]));
}

__global__ void __launch_bounds__(256, 1)
k_gemm_mma(const float* __restrict__ X) {
    __shared__ __half As[128 * AS_STRIDE];
    __shared__ __half Bs[128 * AS_STRIDE];   // rows = output col n, cols = k (W1^T)
    int tid = threadIdx.x;
    int wid = tid >> 5, lane = tid & 31;
    size_t row0 = (size_t)blockIdx.x * 128;

    // load A: X rows row0..+127, fp32 -> fp16
#pragma unroll
    for (int i = 0; i < 32; i++) {
        int idx = tid + i * 256;          // 0..8191 half2 slots
        int row = idx >> 6, c2 = idx & 63;
        float2 xv = *(const float2*)(X + (row0 + row) * ND + c2 * 2);
        *(__half2*)(As + row * AS_STRIDE + c2 * 2) = __floats2half2_rn(xv.x, xv.y);
    }
    // load B: W1^T fp16 (row n, contiguous k)
#pragma unroll
    for (int i = 0; i < 32; i++) {
        int idx = tid + i * 256;
        int n = idx >> 6, c2 = idx & 63;
        *(__half2*)(Bs + n * AS_STRIDE + c2 * 2) =
            *(const __half2*)(g_w1h + n * ND + c2 * 2);
    }
    __syncthreads();

    int wr = (wid & 3) * 32;   // warp row block within CTA
    int wc = (wid >> 2) * 64;  // warp col block
    int grp = lane >> 2;       // 0..7
    int tig = lane & 3;        // 0..3

    float acc[2][8][4];
#pragma unroll
    for (int mt = 0; mt < 2; mt++)
#pragma unroll
        for (int nt = 0; nt < 8; nt++)
#pragma unroll
            for (int q = 0; q < 4; q++) acc[mt][nt][q] = 0.f;

#pragma unroll
    for (int kc = 0; kc < 8; kc++) {
        int k0 = kc * 16;
        uint32_t a[2][4];
#pragma unroll
        for (int mt = 0; mt < 2; mt++) {
            const __half* base = As + (wr + mt * 16) * AS_STRIDE + k0;
            a[mt][0] = *(const uint32_t*)(base + grp * AS_STRIDE + tig * 2);
            a[mt][1] = *(const uint32_t*)(base + (grp + 8) * AS_STRIDE + tig * 2);
            a[mt][2] = *(const uint32_t*)(base + grp * AS_STRIDE + tig * 2 + 8);
            a[mt][3] = *(const uint32_t*)(base + (grp + 8) * AS_STRIDE + tig * 2 + 8);
        }
#pragma unroll
        for (int nt = 0; nt < 8; nt++) {
            uint32_t b[2];
            const __half* bb = Bs + (wc + nt * 8 + grp) * AS_STRIDE + k0;
            b[0] = *(const uint32_t*)(bb + tig * 2);
            b[1] = *(const uint32_t*)(bb + tig * 2 + 8);
            mma16816(acc[0][nt], a[0], b);
            mma16816(acc[1][nt], a[1], b);
        }
    }

    // epilogue: fp32 -> fp16 direct stores
#pragma unroll
    for (int mt = 0; mt < 2; mt++) {
        size_t r0 = row0 + wr + mt * 16 + grp;
#pragma unroll
        for (int nt = 0; nt < 8; nt++) {
            int col = wc + nt * 8 + tig * 2;
            __half2 lo = __floats2half2_rn(acc[mt][nt][0], acc[mt][nt][1]);
            __half2 hi = __floats2half2_rn(acc[mt][nt][2], acc[mt][nt][3]);
            *(__half2*)(g_h1 + r0 * ND + col)       = lo;
            *(__half2*)(g_h1 + (r0 + 8) * ND + col) = hi;
        }
    }
}

// ---------------- fused agg + bias + relu + weighted pool partial (fp16 gather) ----------------
__global__ void k_agg(const float* __restrict__ b1) {
    int b = blockIdx.y;
    int d2 = threadIdx.x;                   // 0..63
    int dst0 = blockIdx.x * CHUNK;
    int dst1 = min(dst0 + CHUNK, NN);
    const __half2* __restrict__ hb = (const __half2*)(g_h1 + (size_t)b * NN * ND);
    float bx = b1[2 * d2], by = b1[2 * d2 + 1];
    float vx = 0.f, vy = 0.f;

    for (int dst = dst0; dst < dst1; ++dst) {
        float sn = g_selfn[dst];
        float2 hs = __half22float2(hb[dst * 64 + d2]);
        float ax = fmaf(sn, hs.x, bx);
        float ay = fmaf(sn, hs.y, by);
        int s = g_rs[dst], e = g_rs[dst + 1];
        int i = s;
        for (; i + 4 <= e; i += 4) {
            int2 e0 = g_csr[i], e1 = g_csr[i + 1], e2 = g_csr[i + 2], e3 = g_csr[i + 3];
            float2 h0 = __half22float2(hb[e0.x + d2]);
            float2 h1v = __half22float2(hb[e1.x + d2]);
            float2 h2v = __half22float2(hb[e2.x + d2]);
            float2 h3v = __half22float2(hb[e3.x + d2]);
            float w0 = __int_as_float(e0.y), w1 = __int_as_float(e1.y);
            float w2 = __int_as_float(e2.y), w3 = __int_as_float(e3.y);
            ax = fmaf(w0, h0.x, ax);  ay = fmaf(w0, h0.y, ay);
            ax = fmaf(w1, h1v.x, ax); ay = fmaf(w1, h1v.y, ay);
            ax = fmaf(w2, h2v.x, ax); ay = fmaf(w2, h2v.y, ay);
            ax = fmaf(w3, h3v.x, ax); ay = fmaf(w3, h3v.y, ay);
        }
        for (; i < e; ++i) {
            int2 ee = g_csr[i];
            float2 h = __half22float2(hb[ee.x + d2]);
            float w = __int_as_float(ee.y);
            ax = fmaf(w, h.x, ax);
            ay = fmaf(w, h.y, ay);
        }
        ax = fmaxf(ax, 0.f);
        ay = fmaxf(ay, 0.f);
        float c = g_c[dst];
        vx = fmaf(c, ax, vx);
        vy = fmaf(c, ay, vy);
    }
    atomicAdd(&g_v[b * ND + 2 * d2],     vx);
    atomicAdd(&g_v[b * ND + 2 * d2 + 1], vy);
}

// ---------------- final: out[b,:] = (v[b,:]/N) @ W2 + b2 ----------------
__global__ void k_final(const float* __restrict__ W2, const float* __restrict__ b2,
                        float* __restrict__ out) {
    __shared__ float vs[ND];
    int b = blockIdx.x, d = threadIdx.x;
    vs[d] = g_v[b * ND + d] * (1.0f / NN);
    __syncthreads();
    float acc = b2[d];
#pragma unroll 8
    for (int k = 0; k < ND; k++) acc = fmaf(vs[k], W2[k * ND + d], acc);
    out[b * ND + d] = acc;
}

// ---------------- launch ----------------
extern "C" void kernel_launch(void* const* d_in, const int* in_sizes, int n_in,
                              void* d_out, int out_size) {
    const float* gene = (const float*)d_in[0];
    const int*   esrc = (const int*)d_in[1];
    const int*   edst = (const int*)d_in[2];
    const float* W1   = (const float*)d_in[3];
    const float* b1   = (const float*)d_in[4];
    const float* W2   = (const float*)d_in[5];
    const float* b2   = (const float*)d_in[6];
    float* out = (float*)d_out;

    k_prep0<<<64, 256>>>(W1);                              // 1
    k_count<<<(NE + 255) / 256, 256>>>(edst);              // 2
    k_scandinv<<<1, 1024>>>();                             // 3
    k_scatter<<<(NE + 255) / 256, 256>>>(esrc, edst);      // 4
    k_gemm_mma<<<(NB * NN) / 128, 256>>>(gene);            // 5
    dim3 agrid((NN + CHUNK - 1) / CHUNK, NB);
    k_agg<<<agrid, 64>>>(b1);                              // 6  <- ncu profiles this
    k_final<<<NB, ND>>>(W2, b2, out);                      // 7
}